// round 1
// baseline (speedup 1.0000x reference)
#include <cuda_runtime.h>
#include <cstdint>

#define HEADS 8
#define SEQ   4096
#define DQK   96
#define DV    64
#define ATTN_SCALE 0.17677669529663689f   // (256/8)^-0.5

// ---------------- scratch (device globals: no allocation allowed) ----------
__device__ float Qg[(size_t)HEADS * SEQ * DQK];   // [h][n][96], pre-scaled by ATTN_SCALE
__device__ float Kg[(size_t)HEADS * SEQ * DQK];   // [h][n][96]
__device__ float Vtg[(size_t)HEADS * DV * SEQ];   // [h*64+d][n]  (transposed V)

// ---------------- helpers --------------------------------------------------
__device__ __forceinline__ float to_tf32(float x) {
    uint32_t u;
    asm("cvt.rna.tf32.f32 %0, %1;" : "=r"(u) : "f"(x));
    return __uint_as_float(u);
}
__device__ __forceinline__ uint32_t fbits(float x) { return __float_as_uint(x); }

// D = A(16x8, tf32, row) * B(8x8, tf32, col) + D  (f32 accum)
__device__ __forceinline__ void mma8(float c[4],
                                     uint32_t a0, uint32_t a1, uint32_t a2, uint32_t a3,
                                     uint32_t b0, uint32_t b1) {
    asm volatile(
        "mma.sync.aligned.m16n8k8.row.col.f32.tf32.tf32.f32 "
        "{%0,%1,%2,%3}, {%4,%5,%6,%7}, {%8,%9}, {%0,%1,%2,%3};"
        : "+f"(c[0]), "+f"(c[1]), "+f"(c[2]), "+f"(c[3])
        : "r"(a0), "r"(a1), "r"(a2), "r"(a3), "r"(b0), "r"(b1));
}

// ---------------- projection GEMMs (tf32 mma) ------------------------------
// C[M=4096 x Nc] = A[4096 x K] * W[K x Nc], 64x64 CTA tile, BK=32, 4 warps.
// EPI 0: qk projection -> Qg (cols 0..767, *SCALE) / Kg (cols 768..1535)
// EPI 1: v  projection -> Vtg (transposed store)
template <int EPI>
__global__ __launch_bounds__(128) void proj_gemm(const float* __restrict__ A,
                                                 const float* __restrict__ W,
                                                 int K, int Nc) {
    __shared__ float As[64][36];   // stride 36 (= 4 mod 32): conflict-free frags
    __shared__ float Ws[32][68];   // stride 68 (= 4 mod 32)

    const int tid  = threadIdx.x;
    const int w    = tid >> 5;
    const int lane = tid & 31;
    const int g    = lane >> 2;
    const int t    = lane & 3;
    const int m0   = blockIdx.y * 64;
    const int n0   = blockIdx.x * 64;

    float acc[8][4];
#pragma unroll
    for (int i = 0; i < 8; i++)
#pragma unroll
        for (int j = 0; j < 4; j++) acc[i][j] = 0.f;

    for (int kt = 0; kt < K; kt += 32) {
        // A tile 64x32
#pragma unroll
        for (int i = 0; i < 4; i++) {
            int idx = tid + i * 128;                 // 0..511
            int r = idx >> 3, c = (idx & 7) * 4;
            float4 v = *reinterpret_cast<const float4*>(&A[(size_t)(m0 + r) * K + kt + c]);
            As[r][c + 0] = to_tf32(v.x); As[r][c + 1] = to_tf32(v.y);
            As[r][c + 2] = to_tf32(v.z); As[r][c + 3] = to_tf32(v.w);
        }
        // W tile 32x64
#pragma unroll
        for (int i = 0; i < 4; i++) {
            int idx = tid + i * 128;
            int r = idx >> 4, c = (idx & 15) * 4;
            float4 v = *reinterpret_cast<const float4*>(&W[(size_t)(kt + r) * Nc + n0 + c]);
            Ws[r][c + 0] = to_tf32(v.x); Ws[r][c + 1] = to_tf32(v.y);
            Ws[r][c + 2] = to_tf32(v.z); Ws[r][c + 3] = to_tf32(v.w);
        }
        __syncthreads();
#pragma unroll
        for (int ks = 0; ks < 4; ks++) {
            uint32_t a0 = fbits(As[w * 16 + g][ks * 8 + t]);
            uint32_t a1 = fbits(As[w * 16 + g + 8][ks * 8 + t]);
            uint32_t a2 = fbits(As[w * 16 + g][ks * 8 + t + 4]);
            uint32_t a3 = fbits(As[w * 16 + g + 8][ks * 8 + t + 4]);
#pragma unroll
            for (int nf = 0; nf < 8; nf++) {
                uint32_t b0 = fbits(Ws[ks * 8 + t][nf * 8 + g]);
                uint32_t b1 = fbits(Ws[ks * 8 + t + 4][nf * 8 + g]);
                mma8(acc[nf], a0, a1, a2, a3, b0, b1);
            }
        }
        __syncthreads();
    }

    // epilogue
#pragma unroll
    for (int nf = 0; nf < 8; nf++) {
#pragma unroll
        for (int j = 0; j < 4; j++) {
            int row = m0 + w * 16 + g + (j >> 1) * 8;
            int col = n0 + nf * 8 + 2 * t + (j & 1);
            float v = acc[nf][j];
            if (EPI == 0) {
                if (col < 768) {
                    int h = col / 96, d = col - h * 96;
                    Qg[((size_t)h * SEQ + row) * DQK + d] = v * ATTN_SCALE;
                } else {
                    int cc = col - 768;
                    int h = cc / 96, d = cc - h * 96;
                    Kg[((size_t)h * SEQ + row) * DQK + d] = v;
                }
            } else {
                Vtg[(size_t)col * SEQ + row] = v;
            }
        }
    }
}

// ---------------- fused masked flash attention -----------------------------
#define KS_STRIDE 100   // 96+4, = 4 mod 32
#define VS_STRIDE 68    // 64+4
#define PS_STRIDE 68

__global__ __launch_bounds__(128) void attn_kernel(const float* __restrict__ masks,
                                                   float* __restrict__ out) {
    extern __shared__ float sm[];
    float* Ks = sm;                                 // 64 x 100 (tf32-rounded K tile)
    float* Vs = sm + 64 * KS_STRIDE;                // 64 x 68  (V^T tile: [d][key])
    float* Ps = Vs + 64 * VS_STRIDE;                // 4 warps x 16 x 68 (P~ tiles)

    const int tid  = threadIdx.x;
    const int w    = tid >> 5;
    const int lane = tid & 31;
    const int g    = lane >> 2;
    const int t    = lane & 3;
    const int h    = blockIdx.x;        // head fastest -> mask rows shared in L2
    const int q0   = blockIdx.y * 64;
    const int row0 = q0 + w * 16 + g;   // thread's first query row (second = +8)

    const float* Qbase = &Qg[(size_t)h * SEQ * DQK];
    const float* Kbase = &Kg[(size_t)h * SEQ * DQK];
    const float* Vbase = &Vtg[(size_t)h * DV * SEQ];
    float* Pw = Ps + w * 16 * PS_STRIDE;

    // preload Q fragments for all 12 k-slices (Q already scaled by ATTN_SCALE)
    uint32_t qa[12][4];
#pragma unroll
    for (int ks = 0; ks < 12; ks++) {
        qa[ks][0] = fbits(to_tf32(Qbase[(size_t)row0 * DQK + ks * 8 + t]));
        qa[ks][1] = fbits(to_tf32(Qbase[(size_t)(row0 + 8) * DQK + ks * 8 + t]));
        qa[ks][2] = fbits(to_tf32(Qbase[(size_t)row0 * DQK + ks * 8 + t + 4]));
        qa[ks][3] = fbits(to_tf32(Qbase[(size_t)(row0 + 8) * DQK + ks * 8 + t + 4]));
    }

    float o[8][4];
#pragma unroll
    for (int i = 0; i < 8; i++)
#pragma unroll
        for (int j = 0; j < 4; j++) o[i][j] = 0.f;

    float mrow0 = -1e30f, mrow1 = -1e30f;   // running row max (2 rows / thread)
    float z0 = 0.f, z1 = 0.f;               // running exp-sums (thread-partial over quad)
    float ws0 = 0.f, ws1 = 0.f;             // mask row-sums   (thread-partial over quad)

#pragma unroll 1
    for (int kt = 0; kt < SEQ; kt += 64) {
        __syncthreads();
        // K tile: 64 keys x 96, tf32-rounded into smem
#pragma unroll
        for (int i = 0; i < 12; i++) {
            int idx = tid + i * 128;          // 0..1535
            int r = idx / 24, c = (idx % 24) * 4;
            float4 v = *reinterpret_cast<const float4*>(&Kbase[(size_t)(kt + r) * DQK + c]);
            float* dst = &Ks[r * KS_STRIDE + c];
            dst[0] = to_tf32(v.x); dst[1] = to_tf32(v.y);
            dst[2] = to_tf32(v.z); dst[3] = to_tf32(v.w);
        }
        // V tile (already transposed in gmem): Vs[d][key]
#pragma unroll
        for (int i = 0; i < 8; i++) {
            int idx = tid + i * 128;          // 0..1023
            int r = idx >> 4, c = (idx & 15) * 4;
            float4 v = *reinterpret_cast<const float4*>(&Vbase[(size_t)r * SEQ + kt + c]);
            float* dst = &Vs[r * VS_STRIDE + c];
            dst[0] = to_tf32(v.x); dst[1] = to_tf32(v.y);
            dst[2] = to_tf32(v.z); dst[3] = to_tf32(v.w);
        }
        __syncthreads();

        // S = Q K^T  (16x64 per warp)
        float s[8][4];
#pragma unroll
        for (int i = 0; i < 8; i++)
#pragma unroll
            for (int j = 0; j < 4; j++) s[i][j] = 0.f;
#pragma unroll
        for (int ks = 0; ks < 12; ks++) {
#pragma unroll
            for (int nf = 0; nf < 8; nf++) {
                uint32_t b0 = fbits(Ks[(nf * 8 + g) * KS_STRIDE + ks * 8 + t]);
                uint32_t b1 = fbits(Ks[(nf * 8 + g) * KS_STRIDE + ks * 8 + t + 4]);
                mma8(s[nf], qa[ks][0], qa[ks][1], qa[ks][2], qa[ks][3], b0, b1);
            }
        }

        // online softmax: tile row max -> quad reduce
        float tm0 = -1e30f, tm1 = -1e30f;
#pragma unroll
        for (int nf = 0; nf < 8; nf++) {
            tm0 = fmaxf(tm0, fmaxf(s[nf][0], s[nf][1]));
            tm1 = fmaxf(tm1, fmaxf(s[nf][2], s[nf][3]));
        }
        tm0 = fmaxf(tm0, __shfl_xor_sync(0xffffffffu, tm0, 1));
        tm0 = fmaxf(tm0, __shfl_xor_sync(0xffffffffu, tm0, 2));
        tm1 = fmaxf(tm1, __shfl_xor_sync(0xffffffffu, tm1, 1));
        tm1 = fmaxf(tm1, __shfl_xor_sync(0xffffffffu, tm1, 2));
        float mn0 = fmaxf(mrow0, tm0), mn1 = fmaxf(mrow1, tm1);
        float al0 = __expf(mrow0 - mn0), al1 = __expf(mrow1 - mn1);

        const float2* mp0 = reinterpret_cast<const float2*>(&masks[(size_t)row0 * SEQ + kt]);
        const float2* mp1 = reinterpret_cast<const float2*>(&masks[(size_t)(row0 + 8) * SEQ + kt]);

        float zp0 = 0.f, zp1 = 0.f;
#pragma unroll
        for (int nf = 0; nf < 8; nf++) {
            float2 mv0 = __ldg(&mp0[nf * 4 + t]);
            float2 mv1 = __ldg(&mp1[nf * 4 + t]);
            float p00 = __expf(s[nf][0] - mn0);
            float p01 = __expf(s[nf][1] - mn0);
            float p10 = __expf(s[nf][2] - mn1);
            float p11 = __expf(s[nf][3] - mn1);
            zp0 += p00 + p01;  zp1 += p10 + p11;
            ws0 += mv0.x + mv0.y;  ws1 += mv1.x + mv1.y;
            float2 pw0 = make_float2(to_tf32(p00 * mv0.x), to_tf32(p01 * mv0.y));
            float2 pw1 = make_float2(to_tf32(p10 * mv1.x), to_tf32(p11 * mv1.y));
            *reinterpret_cast<float2*>(&Pw[g * PS_STRIDE + nf * 8 + 2 * t]) = pw0;
            *reinterpret_cast<float2*>(&Pw[(g + 8) * PS_STRIDE + nf * 8 + 2 * t]) = pw1;
        }
        z0 = z0 * al0 + zp0;
        z1 = z1 * al1 + zp1;
#pragma unroll
        for (int nf = 0; nf < 8; nf++) {
            o[nf][0] *= al0; o[nf][1] *= al0;
            o[nf][2] *= al1; o[nf][3] *= al1;
        }
        mrow0 = mn0; mrow1 = mn1;
        __syncwarp();

        // O += P~ @ V  (K-dim = 64 keys -> 8 k-slices)
#pragma unroll
        for (int kq = 0; kq < 8; kq++) {
            uint32_t a0 = fbits(Pw[g * PS_STRIDE + kq * 8 + t]);
            uint32_t a1 = fbits(Pw[(g + 8) * PS_STRIDE + kq * 8 + t]);
            uint32_t a2 = fbits(Pw[g * PS_STRIDE + kq * 8 + t + 4]);
            uint32_t a3 = fbits(Pw[(g + 8) * PS_STRIDE + kq * 8 + t + 4]);
#pragma unroll
            for (int nf = 0; nf < 8; nf++) {
                uint32_t b0 = fbits(Vs[(nf * 8 + g) * VS_STRIDE + kq * 8 + t]);
                uint32_t b1 = fbits(Vs[(nf * 8 + g) * VS_STRIDE + kq * 8 + t + 4]);
                mma8(o[nf], a0, a1, a2, a3, b0, b1);
            }
        }
    }

    // final quad reductions + scaling: out = O / (Z * 8 * Wsum)
    z0 += __shfl_xor_sync(0xffffffffu, z0, 1);  z0 += __shfl_xor_sync(0xffffffffu, z0, 2);
    z1 += __shfl_xor_sync(0xffffffffu, z1, 1);  z1 += __shfl_xor_sync(0xffffffffu, z1, 2);
    ws0 += __shfl_xor_sync(0xffffffffu, ws0, 1); ws0 += __shfl_xor_sync(0xffffffffu, ws0, 2);
    ws1 += __shfl_xor_sync(0xffffffffu, ws1, 1); ws1 += __shfl_xor_sync(0xffffffffu, ws1, 2);
    float inv0 = 1.f / (z0 * 8.f * ws0);
    float inv1 = 1.f / (z1 * 8.f * ws1);

#pragma unroll
    for (int nf = 0; nf < 8; nf++) {
        int col = h * 64 + nf * 8 + 2 * t;
        float2 o0 = make_float2(o[nf][0] * inv0, o[nf][1] * inv0);
        float2 o1 = make_float2(o[nf][2] * inv1, o[nf][3] * inv1);
        *reinterpret_cast<float2*>(&out[(size_t)row0 * 512 + col]) = o0;
        *reinterpret_cast<float2*>(&out[(size_t)(row0 + 8) * 512 + col]) = o1;
    }
}

// ---------------- launch ---------------------------------------------------
extern "C" void kernel_launch(void* const* d_in, const int* in_sizes, int n_in,
                              void* d_out, int out_size) {
    const float* qk    = (const float*)d_in[0];   // (1, 4096, 768)
    const float* v_cls = (const float*)d_in[1];   // (1, 4096, 512)
    const float* masks = (const float*)d_in[2];   // (1, 4096, 4096)
    const float* W_qk  = (const float*)d_in[3];   // (768, 1536)
    const float* W_v   = (const float*)d_in[4];   // (512, 512)
    float* out = (float*)d_out;                   // (1, 4096, 512)

    proj_gemm<0><<<dim3(24, 64), 128>>>(qk, W_qk, 768, 1536);
    proj_gemm<1><<<dim3(8, 64), 128>>>(v_cls, W_v, 512, 512);

    const int smem_bytes =
        (64 * KS_STRIDE + 64 * VS_STRIDE + 4 * 16 * PS_STRIDE) * (int)sizeof(float); // 60416
    cudaFuncSetAttribute(attn_kernel, cudaFuncAttributeMaxDynamicSharedMemorySize, smem_bytes);
    attn_kernel<<<dim3(8, 64), 128, smem_bytes>>>(masks, out);
}